// round 10
// baseline (speedup 1.0000x reference)
#include <cuda_runtime.h>
#include <cuda_bf16.h>
#include <cstdint>

#define BSZ 4096
#define D 128
#define TWO_B 8192
#define NRB 64
#define NTHREADS 512
#define NCTAS 148

#define LDS_ELEM 136
#define LDS_BYTES (LDS_ELEM * 2)
#define TILE_BYTES (128 * LDS_BYTES)

#define OFF_A    0
#define OFF_B0   TILE_BYTES
#define OFF_B1   (2 * TILE_BYTES)
#define SMEM_TOTAL (3 * TILE_BYTES)

#define EXP_SCALE 2.8853900817779268f   // 2*log2(e): exp(2s) = ex2(s*EXP_SCALE)

__device__ __align__(256) __nv_bfloat16 g_Zbf16[TWO_B * D];
__device__ float g_pos[BSZ];
__device__ float g_denom[TWO_B];
__device__ unsigned int g_done = 0;

static __device__ __forceinline__ uint32_t smem_u32(const void* p) {
    uint32_t a;
    asm("{ .reg .u64 t; cvta.to.shared.u64 t, %1; cvt.u32.u64 %0, t; }"
        : "=r"(a) : "l"(p));
    return a;
}

#define CP_ASYNC16(dst, src) \
    asm volatile("cp.async.cg.shared.global [%0], [%1], 16;" :: "r"(dst), "l"(src))
#define CP_COMMIT()   asm volatile("cp.async.commit_group;" ::: "memory")
#define CP_WAIT(n)    asm volatile("cp.async.wait_group %0;" :: "n"(n) : "memory")

#define LDM_X4(r0, r1, r2, r3, addr) \
    asm volatile("ldmatrix.sync.aligned.m8n8.x4.shared.b16 {%0,%1,%2,%3}, [%4];" \
                 : "=r"(r0), "=r"(r1), "=r"(r2), "=r"(r3) : "r"(addr))

#define MMA_BF16(c0, c1, c2, c3, a0, a1, a2, a3, b0, b1) \
    asm volatile("mma.sync.aligned.m16n8k16.row.col.f32.bf16.bf16.f32 " \
                 "{%0,%1,%2,%3}, {%4,%5,%6,%7}, {%8,%9}, {%0,%1,%2,%3};" \
                 : "+f"(c0), "+f"(c1), "+f"(c2), "+f"(c3) \
                 : "r"(a0), "r"(a1), "r"(a2), "r"(a3), "r"(b0), "r"(b1))

static __device__ __forceinline__ float ex2f(float x) {
    float r;
    asm("ex2.approx.ftz.f32 %0, %1;" : "=f"(r) : "f"(x));
    return r;
}

// ---------------------------------------------------------------------------
// Kernel 1: normalize; emit bf16 z; fp32 positives; zero g_denom.
// ---------------------------------------------------------------------------
__global__ void normalize_kernel(const float* __restrict__ p1,
                                 const float* __restrict__ p2) {
    int gid  = blockIdx.x * blockDim.x + threadIdx.x;
    if (gid < TWO_B) g_denom[gid] = 0.0f;

    int warp = gid >> 5;
    int lane = threadIdx.x & 31;
    if (warp >= BSZ) return;

    float4 a = *(const float4*)&p1[warp * D + lane * 4];
    float4 b = *(const float4*)&p2[warp * D + lane * 4];

    float ss1 = a.x*a.x + a.y*a.y + a.z*a.z + a.w*a.w;
    float ss2 = b.x*b.x + b.y*b.y + b.z*b.z + b.w*b.w;
    #pragma unroll
    for (int o = 16; o > 0; o >>= 1) {
        ss1 += __shfl_xor_sync(0xFFFFFFFFu, ss1, o);
        ss2 += __shfl_xor_sync(0xFFFFFFFFu, ss2, o);
    }
    float r1 = rsqrtf(fmaxf(ss1, 1e-16f));
    float r2 = rsqrtf(fmaxf(ss2, 1e-16f));

    float4 z1 = make_float4(a.x*r1, a.y*r1, a.z*r1, a.w*r1);
    float4 z2 = make_float4(b.x*r2, b.y*r2, b.z*r2, b.w*r2);

    __nv_bfloat162* o1 = (__nv_bfloat162*)&g_Zbf16[warp * D + lane * 4];
    __nv_bfloat162* o2 = (__nv_bfloat162*)&g_Zbf16[(warp + BSZ) * D + lane * 4];
    o1[0] = __floats2bfloat162_rn(z1.x, z1.y);
    o1[1] = __floats2bfloat162_rn(z1.z, z1.w);
    o2[0] = __floats2bfloat162_rn(z2.x, z2.y);
    o2[1] = __floats2bfloat162_rn(z2.z, z2.w);

    float d = z1.x*z2.x + z1.y*z2.y + z1.z*z2.z + z1.w*z2.w;
    #pragma unroll
    for (int o = 16; o > 0; o >>= 1)
        d += __shfl_xor_sync(0xFFFFFFFFu, d, o);
    if (lane == 0) g_pos[warp] = d;
}

// one epilogue element e (0..15) of half hf: mi = e>>3, ni = (e>>2)&1, q = e&3
#define EPI_ELEM(hf, e) do {                                                  \
    int mi_ = (e) >> 3, ni_ = (((e) >> 2) & 1), q_ = (e) & 3;                 \
    float ev_ = ex2f(c[mi_][(hf) * 2 + ni_][q_] * EXP_SCALE);                 \
    rowacc[mi_ * 2 + (q_ >> 1)] += ev_;                                       \
    colacc[((hf) * 2 + ni_) * 2 + (q_ & 1)] += ev_;                           \
} while (0)

// ---------------------------------------------------------------------------
// Kernel 2: upper-triangle HMMA + fused ex2 rowsum/colsum + fused finalize.
// 512 threads (16 warps, 4x4 warp grid, warp tile 32x32) = 4 warps/SMSP.
// Scheduling/flush logic identical to the proven R7 kernel.
// ---------------------------------------------------------------------------
__global__ void __launch_bounds__(NTHREADS, 1) simsum_tri_kernel(float* __restrict__ out) {
    extern __shared__ char smem[];
    const uint32_t sbase = smem_u32(smem);
    const int tid  = threadIdx.x;
    const int lane = tid & 31;
    const int wid  = tid >> 5;
    const int wm = wid >> 2;                  // 0..3 (row quarter, 32 rows)
    const int wn = wid & 3;                   // 0..3 (col quarter, 32 cols)
    const int bid = blockIdx.x;

    const int cnt   = 14 + (bid < 8 ? 1 : 0);
    const int start = bid * 14 + (bid < 8 ? bid : 8);

    int r;
    {
        float fr = (129.0f - sqrtf(129.0f * 129.0f - 8.0f * (float)start)) * 0.5f;
        r = (int)fr;
        if (r < 0) r = 0;
        if (r > 63) r = 63;
        while (r < 63 && (r + 1) * (129 - (r + 1)) / 2 <= start) ++r;
        while (r > 0 && r * (129 - r) / 2 > start) --r;
    }
    int j = r + (start - r * (129 - r) / 2);

    const uint32_t a_base = sbase + OFF_A +
        (uint32_t)((wm * 32 + (lane & 15)) * LDS_BYTES + (lane >> 4) * 16);
    const uint32_t b_base_rel =
        (uint32_t)((wn * 32 + (lane & 15)) * LDS_BYTES + (lane >> 4) * 16);
    const int groupid = lane >> 2;

    // prefetch B tile for j
    #pragma unroll
    for (int it = 0; it < 2; ++it) {
        int idx = it * NTHREADS + tid;
        int rr = idx >> 3, cc = idx & 7;
        const char* src = (const char*)(g_Zbf16 + (j * 128 + rr) * D + cc * 8);
        CP_ASYNC16(sbase + OFF_B0 + rr * LDS_BYTES + cc * 16, src);
    }
    CP_COMMIT();

    // load A strip r, cache fragments in registers (8 ks x 2 mi x 4)
    uint32_t afr[8][2][4];
    {
        #pragma unroll
        for (int it = 0; it < 2; ++it) {
            int idx = it * NTHREADS + tid;
            int rr = idx >> 3, cc = idx & 7;
            uint4 v = *(const uint4*)(g_Zbf16 + (r * 128 + rr) * D + cc * 8);
            *(uint4*)(smem + OFF_A + rr * LDS_BYTES + cc * 16) = v;
        }
        __syncthreads();
        #pragma unroll
        for (int ks = 0; ks < 8; ++ks)
            #pragma unroll
            for (int mi = 0; mi < 2; ++mi)
                LDM_X4(afr[ks][mi][0], afr[ks][mi][1], afr[ks][mi][2], afr[ks][mi][3],
                       a_base + (uint32_t)(mi * 16 * LDS_BYTES + ks * 32));
    }

    float rowacc[4];
    #pragma unroll
    for (int i = 0; i < 4; ++i) rowacc[i] = 0.0f;

    for (int t = 0; t < cnt; ++t) {
        int rn = r, jn = j + 1;
        if (jn >= NRB) { rn = r + 1; jn = rn; }

        if (t + 1 < cnt) {
            uint32_t bdst = sbase + (((t + 1) & 1) ? OFF_B1 : OFF_B0);
            #pragma unroll
            for (int it = 0; it < 2; ++it) {
                int idx = it * NTHREADS + tid;
                int rr = idx >> 3, cc = idx & 7;
                const char* src = (const char*)(g_Zbf16 + (jn * 128 + rr) * D + cc * 8);
                CP_ASYNC16(bdst + rr * LDS_BYTES + cc * 16, src);
            }
            CP_COMMIT();
            CP_WAIT(1);
        } else {
            CP_WAIT(0);
        }
        __syncthreads();

        const uint32_t b_base = sbase + ((t & 1) ? OFF_B1 : OFF_B0) + b_base_rel;

        float c[2][4][4];
        float colacc[8];
        #pragma unroll
        for (int i = 0; i < 8; ++i) colacc[i] = 0.0f;

        // ---- pass 0: MMA for ni = 0..1 (b half 0) ----
        #pragma unroll
        for (int mi = 0; mi < 2; ++mi)
            #pragma unroll
            for (int ni = 0; ni < 2; ++ni)
                #pragma unroll
                for (int q = 0; q < 4; ++q) c[mi][ni][q] = 0.0f;
        #pragma unroll
        for (int ks = 0; ks < 8; ++ks) {
            uint32_t b0[4];
            LDM_X4(b0[0], b0[1], b0[2], b0[3], b_base + (uint32_t)(ks * 32));
            #pragma unroll
            for (int mi = 0; mi < 2; ++mi)
                #pragma unroll
                for (int ni = 0; ni < 2; ++ni)
                    MMA_BF16(c[mi][ni][0], c[mi][ni][1], c[mi][ni][2], c[mi][ni][3],
                             afr[ks][mi][0], afr[ks][mi][1], afr[ks][mi][2], afr[ks][mi][3],
                             b0[ni], b0[ni + 2]);
        }

        // ---- pass 1: MMA for ni = 2..3 with half0 epilogue interleaved ----
        #pragma unroll
        for (int mi = 0; mi < 2; ++mi)
            #pragma unroll
            for (int ni = 2; ni < 4; ++ni)
                #pragma unroll
                for (int q = 0; q < 4; ++q) c[mi][ni][q] = 0.0f;
        #pragma unroll
        for (int ks = 0; ks < 8; ++ks) {
            uint32_t b1[4];
            LDM_X4(b1[0], b1[1], b1[2], b1[3],
                   b_base + (uint32_t)(16 * LDS_BYTES + ks * 32));
            #pragma unroll
            for (int mi = 0; mi < 2; ++mi)
                #pragma unroll
                for (int ni = 0; ni < 2; ++ni)
                    MMA_BF16(c[mi][ni + 2][0], c[mi][ni + 2][1], c[mi][ni + 2][2], c[mi][ni + 2][3],
                             afr[ks][mi][0], afr[ks][mi][1], afr[ks][mi][2], afr[ks][mi][3],
                             b1[ni], b1[ni + 2]);
            // 2 half0 epilogue elements per ks iteration (16 total)
            EPI_ELEM(0, ks * 2 + 0);
            EPI_ELEM(0, ks * 2 + 1);
        }

        // ---- half1 epilogue tail ----
        #pragma unroll
        for (int e = 0; e < 16; ++e) EPI_ELEM(1, e);

        // flush colsums unless diagonal tile
        if (j != r) {
            #pragma unroll
            for (int i = 0; i < 8; ++i) {
                colacc[i] += __shfl_xor_sync(0xFFFFFFFFu, colacc[i], 4);
                colacc[i] += __shfl_xor_sync(0xFFFFFFFFu, colacc[i], 8);
                colacc[i] += __shfl_xor_sync(0xFFFFFFFFu, colacc[i], 16);
            }
            if (lane < 4) {
                int cb = j * 128 + wn * 32 + 2 * lane;
                #pragma unroll
                for (int ni = 0; ni < 4; ++ni) {
                    atomicAdd(&g_denom[cb + ni * 8 + 0], colacc[ni * 2 + 0]);
                    atomicAdd(&g_denom[cb + ni * 8 + 1], colacc[ni * 2 + 1]);
                }
            }
        }

        __syncthreads();   // B buffer reuse guard

        if (t + 1 < cnt && rn != r) {
            #pragma unroll
            for (int i = 0; i < 4; ++i) {
                rowacc[i] += __shfl_xor_sync(0xFFFFFFFFu, rowacc[i], 1);
                rowacc[i] += __shfl_xor_sync(0xFFFFFFFFu, rowacc[i], 2);
            }
            if ((lane & 3) == 0) {
                int rb = r * 128 + wm * 32 + groupid;
                #pragma unroll
                for (int mi = 0; mi < 2; ++mi) {
                    atomicAdd(&g_denom[rb + mi * 16 + 0], rowacc[mi * 2 + 0]);
                    atomicAdd(&g_denom[rb + mi * 16 + 8], rowacc[mi * 2 + 1]);
                }
            }
            #pragma unroll
            for (int i = 0; i < 4; ++i) rowacc[i] = 0.0f;

            #pragma unroll
            for (int it = 0; it < 2; ++it) {
                int idx = it * NTHREADS + tid;
                int rr = idx >> 3, cc = idx & 7;
                uint4 v = *(const uint4*)(g_Zbf16 + (rn * 128 + rr) * D + cc * 8);
                *(uint4*)(smem + OFF_A + rr * LDS_BYTES + cc * 16) = v;
            }
            __syncthreads();
            #pragma unroll
            for (int ks = 0; ks < 8; ++ks)
                #pragma unroll
                for (int mi = 0; mi < 2; ++mi)
                    LDM_X4(afr[ks][mi][0], afr[ks][mi][1], afr[ks][mi][2], afr[ks][mi][3],
                           a_base + (uint32_t)(mi * 16 * LDS_BYTES + ks * 32));
        }

        r = rn; j = jn;
    }

    // final rowsum flush (strip of last processed tile)
    #pragma unroll
    for (int i = 0; i < 4; ++i) {
        rowacc[i] += __shfl_xor_sync(0xFFFFFFFFu, rowacc[i], 1);
        rowacc[i] += __shfl_xor_sync(0xFFFFFFFFu, rowacc[i], 2);
    }
    if ((lane & 3) == 0) {
        int lastidx = start + cnt - 1;
        int rr2;
        {
            float fr = (129.0f - sqrtf(129.0f * 129.0f - 8.0f * (float)lastidx)) * 0.5f;
            rr2 = (int)fr;
            if (rr2 < 0) rr2 = 0;
            if (rr2 > 63) rr2 = 63;
            while (rr2 < 63 && (rr2 + 1) * (129 - (rr2 + 1)) / 2 <= lastidx) ++rr2;
            while (rr2 > 0 && rr2 * (129 - rr2) / 2 > lastidx) --rr2;
        }
        int rb = rr2 * 128 + wm * 32 + groupid;
        #pragma unroll
        for (int mi = 0; mi < 2; ++mi) {
            atomicAdd(&g_denom[rb + mi * 16 + 0], rowacc[mi * 2 + 0]);
            atomicAdd(&g_denom[rb + mi * 16 + 8], rowacc[mi * 2 + 1]);
        }
    }

    // ---- fused finalize: last CTA computes the loss ----
    __shared__ unsigned int s_islast;
    __threadfence();
    __syncthreads();
    if (tid == 0)
        s_islast = (atomicAdd(&g_done, 1u) == NCTAS - 1) ? 1u : 0u;
    __syncthreads();

    if (s_islast) {
        __shared__ float red[NTHREADS];
        float s = 0.0f;
        for (int rr = tid; rr < TWO_B; rr += NTHREADS) {
            float denom = __ldcg(&g_denom[rr]) - 7.3890560989306495f;
            float pos = g_pos[rr & (BSZ - 1)];
            s += __logf(fmaxf(denom, 1e-20f)) - 2.0f * pos;
        }
        red[tid] = s;
        __syncthreads();
        #pragma unroll
        for (int st = NTHREADS / 2; st > 0; st >>= 1) {
            if (tid < st) red[tid] += red[tid + st];
            __syncthreads();
        }
        if (tid == 0) {
            out[0] = red[0] / (float)TWO_B;
            g_done = 0;     // reset for next graph replay
        }
    }
}

// ---------------------------------------------------------------------------
extern "C" void kernel_launch(void* const* d_in, const int* in_sizes, int n_in,
                              void* d_out, int out_size) {
    const float* p1 = (const float*)d_in[0];
    const float* p2 = (const float*)d_in[1];
    float* out = (float*)d_out;
    (void)in_sizes; (void)n_in; (void)out_size;

    cudaFuncSetAttribute(simsum_tri_kernel,
                         cudaFuncAttributeMaxDynamicSharedMemorySize,
                         SMEM_TOTAL);

    normalize_kernel<<<BSZ / 16, 512>>>(p1, p2);
    simsum_tri_kernel<<<NCTAS, NTHREADS, SMEM_TOTAL>>>(out);
}

// round 11
// speedup vs baseline: 1.0418x; 1.0418x over previous
#include <cuda_runtime.h>
#include <cuda_bf16.h>
#include <cstdint>

#define BSZ 4096
#define D 128
#define TWO_B 8192
#define NRB 64
#define NTHREADS 256
#define NCTAS 288                       // sum_r ceil((64-r)/8); 2 CTAs/SM

#define LDS_ELEM 136
#define LDS_BYTES (LDS_ELEM * 2)
#define TILE_BYTES (128 * LDS_BYTES)

#define OFF_A    0
#define OFF_B0   TILE_BYTES
#define OFF_B1   (2 * TILE_BYTES)
#define SMEM_TOTAL (3 * TILE_BYTES)     // 104448 B -> 2 CTAs/SM

#define EXP_SCALE 2.8853900817779268f   // 2*log2(e): exp(2s) = ex2(s*EXP_SCALE)

__device__ __align__(256) __nv_bfloat16 g_Zbf16[TWO_B * D];
__device__ float g_pos[BSZ];
__device__ float g_denom[TWO_B];
__device__ unsigned int g_done = 0;

static __device__ __forceinline__ uint32_t smem_u32(const void* p) {
    uint32_t a;
    asm("{ .reg .u64 t; cvta.to.shared.u64 t, %1; cvt.u32.u64 %0, t; }"
        : "=r"(a) : "l"(p));
    return a;
}

#define CP_ASYNC16(dst, src) \
    asm volatile("cp.async.cg.shared.global [%0], [%1], 16;" :: "r"(dst), "l"(src))
#define CP_COMMIT()   asm volatile("cp.async.commit_group;" ::: "memory")
#define CP_WAIT(n)    asm volatile("cp.async.wait_group %0;" :: "n"(n) : "memory")

#define LDM_X4(r0, r1, r2, r3, addr) \
    asm volatile("ldmatrix.sync.aligned.m8n8.x4.shared.b16 {%0,%1,%2,%3}, [%4];" \
                 : "=r"(r0), "=r"(r1), "=r"(r2), "=r"(r3) : "r"(addr))

#define MMA_BF16(c0, c1, c2, c3, a0, a1, a2, a3, b0, b1) \
    asm volatile("mma.sync.aligned.m16n8k16.row.col.f32.bf16.bf16.f32 " \
                 "{%0,%1,%2,%3}, {%4,%5,%6,%7}, {%8,%9}, {%0,%1,%2,%3};" \
                 : "+f"(c0), "+f"(c1), "+f"(c2), "+f"(c3) \
                 : "r"(a0), "r"(a1), "r"(a2), "r"(a3), "r"(b0), "r"(b1))

static __device__ __forceinline__ float ex2f(float x) {
    float r;
    asm("ex2.approx.ftz.f32 %0, %1;" : "=f"(r) : "f"(x));
    return r;
}

// ---------------------------------------------------------------------------
// Kernel 1: normalize; emit bf16 z; fp32 positives; zero g_denom.
// ---------------------------------------------------------------------------
__global__ void normalize_kernel(const float* __restrict__ p1,
                                 const float* __restrict__ p2) {
    int gid  = blockIdx.x * blockDim.x + threadIdx.x;
    if (gid < TWO_B) g_denom[gid] = 0.0f;

    int warp = gid >> 5;
    int lane = threadIdx.x & 31;
    if (warp >= BSZ) return;

    float4 a = *(const float4*)&p1[warp * D + lane * 4];
    float4 b = *(const float4*)&p2[warp * D + lane * 4];

    float ss1 = a.x*a.x + a.y*a.y + a.z*a.z + a.w*a.w;
    float ss2 = b.x*b.x + b.y*b.y + b.z*b.z + b.w*b.w;
    #pragma unroll
    for (int o = 16; o > 0; o >>= 1) {
        ss1 += __shfl_xor_sync(0xFFFFFFFFu, ss1, o);
        ss2 += __shfl_xor_sync(0xFFFFFFFFu, ss2, o);
    }
    float r1 = rsqrtf(fmaxf(ss1, 1e-16f));
    float r2 = rsqrtf(fmaxf(ss2, 1e-16f));

    float4 z1 = make_float4(a.x*r1, a.y*r1, a.z*r1, a.w*r1);
    float4 z2 = make_float4(b.x*r2, b.y*r2, b.z*r2, b.w*r2);

    __nv_bfloat162* o1 = (__nv_bfloat162*)&g_Zbf16[warp * D + lane * 4];
    __nv_bfloat162* o2 = (__nv_bfloat162*)&g_Zbf16[(warp + BSZ) * D + lane * 4];
    o1[0] = __floats2bfloat162_rn(z1.x, z1.y);
    o1[1] = __floats2bfloat162_rn(z1.z, z1.w);
    o2[0] = __floats2bfloat162_rn(z2.x, z2.y);
    o2[1] = __floats2bfloat162_rn(z2.z, z2.w);

    float d = z1.x*z2.x + z1.y*z2.y + z1.z*z2.z + z1.w*z2.w;
    #pragma unroll
    for (int o = 16; o > 0; o >>= 1)
        d += __shfl_xor_sync(0xFFFFFFFFu, d, o);
    if (lane == 0) g_pos[warp] = d;
}

// process one epilogue element e (0..31) of half hf (0 or 1)
#define EPI_ELEM(hf, e) do {                                                  \
    int mi_ = (e) >> 3, ni_ = (((e) >> 2) & 1), q_ = (e) & 3;                 \
    float ev_ = ex2f(c[mi_][(hf) * 2 + ni_][q_] * EXP_SCALE);                 \
    rowacc[mi_ * 2 + (q_ >> 1)] += ev_;                                       \
    colacc[((hf) * 2 + ni_) * 2 + (q_ & 1)] += ev_;                           \
} while (0)

// ---------------------------------------------------------------------------
// Kernel 2: upper-triangle HMMA + fused ex2 rowsum/colsum + fused finalize.
// One block = one chunk of <=8 tiles within a SINGLE strip r. 2 CTAs/SM.
// FULL-tile loaders (2048 x 16B chunks; the half-load bug is fixed).
// ---------------------------------------------------------------------------
__global__ void __launch_bounds__(NTHREADS, 2) simsum_tri_kernel(float* __restrict__ out) {
    extern __shared__ char smem[];
    const uint32_t sbase = smem_u32(smem);
    const int tid  = threadIdx.x;
    const int lane = tid & 31;
    const int wid  = tid >> 5;
    const int wm = wid >> 2;
    const int wn = wid & 3;

    // block -> (strip r, chunk) via integer scan
    int b = blockIdx.x;
    int r = 0;
    #pragma unroll 1
    for (;;) {
        int nch = (NRB - r + 7) >> 3;
        if (b < nch) break;
        b -= nch;
        ++r;
    }
    const int j0  = r + b * 8;
    const int cnt = min(8, NRB - j0);

    const uint32_t a_base = sbase + OFF_A +
        (uint32_t)((wm * 64 + (lane & 15)) * LDS_BYTES + (lane >> 4) * 16);
    const uint32_t b_base_rel =
        (uint32_t)((wn * 32 + (lane & 15)) * LDS_BYTES + (lane >> 4) * 16);
    const int groupid = lane >> 2;

    // prefetch B tile for j0 (FULL tile: 2048 chunks)
    #pragma unroll
    for (int it = 0; it < 8; ++it) {
        int idx = it * NTHREADS + tid;
        int rr = idx >> 4, cc = idx & 15;
        const char* src = (const char*)(g_Zbf16 + (j0 * 128 + rr) * D + cc * 8);
        CP_ASYNC16(sbase + OFF_B0 + rr * LDS_BYTES + cc * 16, src);
    }
    CP_COMMIT();

    // load A strip r into smem (FULL tile, once per block)
    #pragma unroll
    for (int it = 0; it < 8; ++it) {
        int idx = it * NTHREADS + tid;
        int rr = idx >> 4, cc = idx & 15;
        uint4 v = *(const uint4*)(g_Zbf16 + (r * 128 + rr) * D + cc * 8);
        *(uint4*)(smem + OFF_A + rr * LDS_BYTES + cc * 16) = v;
    }

    float rowacc[8];
    #pragma unroll
    for (int i = 0; i < 8; ++i) rowacc[i] = 0.0f;

    for (int t = 0; t < cnt; ++t) {
        const int j = j0 + t;

        if (t + 1 < cnt) {
            uint32_t bdst = sbase + (((t + 1) & 1) ? OFF_B1 : OFF_B0);
            #pragma unroll
            for (int it = 0; it < 8; ++it) {
                int idx = it * NTHREADS + tid;
                int rr = idx >> 4, cc = idx & 15;
                const char* src = (const char*)(g_Zbf16 + ((j + 1) * 128 + rr) * D + cc * 8);
                CP_ASYNC16(bdst + rr * LDS_BYTES + cc * 16, src);
            }
            CP_COMMIT();
            CP_WAIT(1);
        } else {
            CP_WAIT(0);
        }
        __syncthreads();   // B[t] (and A on t=0) visible

        const uint32_t b_base = sbase + ((t & 1) ? OFF_B1 : OFF_B0) + b_base_rel;

        float c[4][4][4];
        float colacc[8];
        #pragma unroll
        for (int i = 0; i < 8; ++i) colacc[i] = 0.0f;

        // ---- pass 0: MMA for ni = 0..1 ----
        #pragma unroll
        for (int mi = 0; mi < 4; ++mi)
            #pragma unroll
            for (int ni = 0; ni < 2; ++ni)
                #pragma unroll
                for (int q = 0; q < 4; ++q) c[mi][ni][q] = 0.0f;
        #pragma unroll
        for (int ks = 0; ks < 8; ++ks) {
            uint32_t a[4][4];
            #pragma unroll
            for (int mi = 0; mi < 4; ++mi)
                LDM_X4(a[mi][0], a[mi][1], a[mi][2], a[mi][3],
                       a_base + (uint32_t)(mi * 16 * LDS_BYTES + ks * 32));
            uint32_t b0[4];
            LDM_X4(b0[0], b0[1], b0[2], b0[3], b_base + (uint32_t)(ks * 32));
            #pragma unroll
            for (int mi = 0; mi < 4; ++mi)
                #pragma unroll
                for (int ni = 0; ni < 2; ++ni)
                    MMA_BF16(c[mi][ni][0], c[mi][ni][1], c[mi][ni][2], c[mi][ni][3],
                             a[mi][0], a[mi][1], a[mi][2], a[mi][3],
                             b0[ni], b0[ni + 2]);
        }

        // ---- pass 1: MMA for ni = 2..3 with half0 epilogue interleaved ----
        #pragma unroll
        for (int mi = 0; mi < 4; ++mi)
            #pragma unroll
            for (int ni = 2; ni < 4; ++ni)
                #pragma unroll
                for (int q = 0; q < 4; ++q) c[mi][ni][q] = 0.0f;
        #pragma unroll
        for (int ks = 0; ks < 8; ++ks) {
            uint32_t a[4][4];
            #pragma unroll
            for (int mi = 0; mi < 4; ++mi)
                LDM_X4(a[mi][0], a[mi][1], a[mi][2], a[mi][3],
                       a_base + (uint32_t)(mi * 16 * LDS_BYTES + ks * 32));
            uint32_t b1[4];
            LDM_X4(b1[0], b1[1], b1[2], b1[3],
                   b_base + (uint32_t)(16 * LDS_BYTES + ks * 32));
            #pragma unroll
            for (int mi = 0; mi < 4; ++mi)
                #pragma unroll
                for (int ni = 0; ni < 2; ++ni)
                    MMA_BF16(c[mi][ni + 2][0], c[mi][ni + 2][1], c[mi][ni + 2][2], c[mi][ni + 2][3],
                             a[mi][0], a[mi][1], a[mi][2], a[mi][3],
                             b1[ni], b1[ni + 2]);
            EPI_ELEM(0, ks * 4 + 0);
            EPI_ELEM(0, ks * 4 + 1);
            EPI_ELEM(0, ks * 4 + 2);
            EPI_ELEM(0, ks * 4 + 3);
        }

        // ---- half1 epilogue tail ----
        #pragma unroll
        for (int e = 0; e < 32; ++e) EPI_ELEM(1, e);

        // flush colsums unless diagonal tile
        if (j != r) {
            #pragma unroll
            for (int i = 0; i < 8; ++i) {
                colacc[i] += __shfl_xor_sync(0xFFFFFFFFu, colacc[i], 4);
                colacc[i] += __shfl_xor_sync(0xFFFFFFFFu, colacc[i], 8);
                colacc[i] += __shfl_xor_sync(0xFFFFFFFFu, colacc[i], 16);
            }
            if (lane < 4) {
                int cb = j * 128 + wn * 32 + 2 * lane;
                #pragma unroll
                for (int ni = 0; ni < 4; ++ni) {
                    atomicAdd(&g_denom[cb + ni * 8 + 0], colacc[ni * 2 + 0]);
                    atomicAdd(&g_denom[cb + ni * 8 + 1], colacc[ni * 2 + 1]);
                }
            }
        }

        __syncthreads();   // B buffer reuse guard
    }

    // rowsum flush (single strip r for the whole block)
    #pragma unroll
    for (int i = 0; i < 8; ++i) {
        rowacc[i] += __shfl_xor_sync(0xFFFFFFFFu, rowacc[i], 1);
        rowacc[i] += __shfl_xor_sync(0xFFFFFFFFu, rowacc[i], 2);
    }
    if ((lane & 3) == 0) {
        int rb = r * 128 + wm * 64 + groupid;
        #pragma unroll
        for (int mi = 0; mi < 4; ++mi) {
            atomicAdd(&g_denom[rb + mi * 16 + 0], rowacc[mi * 2 + 0]);
            atomicAdd(&g_denom[rb + mi * 16 + 8], rowacc[mi * 2 + 1]);
        }
    }

    // ---- fused finalize: last CTA computes the loss ----
    __shared__ unsigned int s_islast;
    __threadfence();
    __syncthreads();
    if (tid == 0)
        s_islast = (atomicAdd(&g_done, 1u) == NCTAS - 1) ? 1u : 0u;
    __syncthreads();

    if (s_islast) {
        __shared__ float red[NTHREADS];
        float s = 0.0f;
        for (int rr = tid; rr < TWO_B; rr += NTHREADS) {
            float denom = __ldcg(&g_denom[rr]) - 7.3890560989306495f;
            float pos = g_pos[rr & (BSZ - 1)];
            s += __logf(fmaxf(denom, 1e-20f)) - 2.0f * pos;
        }
        red[tid] = s;
        __syncthreads();
        #pragma unroll
        for (int st = NTHREADS / 2; st > 0; st >>= 1) {
            if (tid < st) red[tid] += red[tid + st];
            __syncthreads();
        }
        if (tid == 0) {
            out[0] = red[0] / (float)TWO_B;
            g_done = 0;     // reset for next graph replay
        }
    }
}

// ---------------------------------------------------------------------------
extern "C" void kernel_launch(void* const* d_in, const int* in_sizes, int n_in,
                              void* d_out, int out_size) {
    const float* p1 = (const float*)d_in[0];
    const float* p2 = (const float*)d_in[1];
    float* out = (float*)d_out;
    (void)in_sizes; (void)n_in; (void)out_size;

    cudaFuncSetAttribute(simsum_tri_kernel,
                         cudaFuncAttributeMaxDynamicSharedMemorySize,
                         SMEM_TOTAL);

    normalize_kernel<<<BSZ / 8, 256>>>(p1, p2);
    simsum_tri_kernel<<<NCTAS, NTHREADS, SMEM_TOTAL>>>(out);
}

// round 12
// speedup vs baseline: 1.1012x; 1.0571x over previous
#include <cuda_runtime.h>
#include <cuda_bf16.h>
#include <cstdint>

#define BSZ 4096
#define D 128
#define TWO_B 8192
#define NRB 64
#define NTHREADS 256
#define NCTAS 148

#define LDS_ELEM 136
#define LDS_BYTES (LDS_ELEM * 2)
#define TILE_BYTES (128 * LDS_BYTES)

#define OFF_A    0
#define OFF_B0   TILE_BYTES
#define OFF_B1   (2 * TILE_BYTES)
#define OFF_B2   (3 * TILE_BYTES)
#define SMEM_TOTAL (4 * TILE_BYTES)      // 139264 B, 1 CTA/SM

#define EXP_SCALE 2.8853900817779268f    // 2*log2(e): exp(2s) = ex2(s*EXP_SCALE)

__device__ __align__(256) __nv_bfloat16 g_Zbf16[TWO_B * D];   // B side (plain z)
__device__ __align__(256) __nv_bfloat16 g_Zbf16s[TWO_B * D];  // A side (z * EXP_SCALE)
__device__ float g_pos[BSZ];
__device__ float g_denom[TWO_B];
__device__ unsigned int g_done = 0;

static __device__ __forceinline__ uint32_t smem_u32(const void* p) {
    uint32_t a;
    asm("{ .reg .u64 t; cvta.to.shared.u64 t, %1; cvt.u32.u64 %0, t; }"
        : "=r"(a) : "l"(p));
    return a;
}

#define CP_ASYNC16(dst, src) \
    asm volatile("cp.async.cg.shared.global [%0], [%1], 16;" :: "r"(dst), "l"(src))
#define CP_COMMIT()   asm volatile("cp.async.commit_group;" ::: "memory")
#define CP_WAIT(n)    asm volatile("cp.async.wait_group %0;" :: "n"(n) : "memory")

#define LDM_X4(r0, r1, r2, r3, addr) \
    asm volatile("ldmatrix.sync.aligned.m8n8.x4.shared.b16 {%0,%1,%2,%3}, [%4];" \
                 : "=r"(r0), "=r"(r1), "=r"(r2), "=r"(r3) : "r"(addr))

#define MMA_BF16(c0, c1, c2, c3, a0, a1, a2, a3, b0, b1) \
    asm volatile("mma.sync.aligned.m16n8k16.row.col.f32.bf16.bf16.f32 " \
                 "{%0,%1,%2,%3}, {%4,%5,%6,%7}, {%8,%9}, {%0,%1,%2,%3};" \
                 : "+f"(c0), "+f"(c1), "+f"(c2), "+f"(c3) \
                 : "r"(a0), "r"(a1), "r"(a2), "r"(a3), "r"(b0), "r"(b1))

static __device__ __forceinline__ float ex2f(float x) {
    float r;
    asm("ex2.approx.ftz.f32 %0, %1;" : "=f"(r) : "f"(x));
    return r;
}

// ---------------------------------------------------------------------------
// Kernel 1: normalize; emit plain bf16 z (B side) + scaled bf16 z (A side),
// fp32 positives; zero g_denom.
// ---------------------------------------------------------------------------
__global__ void normalize_kernel(const float* __restrict__ p1,
                                 const float* __restrict__ p2) {
    int gid  = blockIdx.x * blockDim.x + threadIdx.x;
    if (gid < TWO_B) g_denom[gid] = 0.0f;

    int warp = gid >> 5;
    int lane = threadIdx.x & 31;
    if (warp >= BSZ) return;

    float4 a = *(const float4*)&p1[warp * D + lane * 4];
    float4 b = *(const float4*)&p2[warp * D + lane * 4];

    float ss1 = a.x*a.x + a.y*a.y + a.z*a.z + a.w*a.w;
    float ss2 = b.x*b.x + b.y*b.y + b.z*b.z + b.w*b.w;
    #pragma unroll
    for (int o = 16; o > 0; o >>= 1) {
        ss1 += __shfl_xor_sync(0xFFFFFFFFu, ss1, o);
        ss2 += __shfl_xor_sync(0xFFFFFFFFu, ss2, o);
    }
    float r1 = rsqrtf(fmaxf(ss1, 1e-16f));
    float r2 = rsqrtf(fmaxf(ss2, 1e-16f));

    float4 z1 = make_float4(a.x*r1, a.y*r1, a.z*r1, a.w*r1);
    float4 z2 = make_float4(b.x*r2, b.y*r2, b.z*r2, b.w*r2);

    __nv_bfloat162* o1 = (__nv_bfloat162*)&g_Zbf16[warp * D + lane * 4];
    __nv_bfloat162* o2 = (__nv_bfloat162*)&g_Zbf16[(warp + BSZ) * D + lane * 4];
    o1[0] = __floats2bfloat162_rn(z1.x, z1.y);
    o1[1] = __floats2bfloat162_rn(z1.z, z1.w);
    o2[0] = __floats2bfloat162_rn(z2.x, z2.y);
    o2[1] = __floats2bfloat162_rn(z2.z, z2.w);

    __nv_bfloat162* s1 = (__nv_bfloat162*)&g_Zbf16s[warp * D + lane * 4];
    __nv_bfloat162* s2 = (__nv_bfloat162*)&g_Zbf16s[(warp + BSZ) * D + lane * 4];
    s1[0] = __floats2bfloat162_rn(z1.x * EXP_SCALE, z1.y * EXP_SCALE);
    s1[1] = __floats2bfloat162_rn(z1.z * EXP_SCALE, z1.w * EXP_SCALE);
    s2[0] = __floats2bfloat162_rn(z2.x * EXP_SCALE, z2.y * EXP_SCALE);
    s2[1] = __floats2bfloat162_rn(z2.z * EXP_SCALE, z2.w * EXP_SCALE);

    float d = z1.x*z2.x + z1.y*z2.y + z1.z*z2.z + z1.w*z2.w;
    #pragma unroll
    for (int o = 16; o > 0; o >>= 1)
        d += __shfl_xor_sync(0xFFFFFFFFu, d, o);
    if (lane == 0) g_pos[warp] = d;
}

// one epilogue element e (0..31) of half hf (A pre-scaled: no FMUL needed)
#define EPI_ELEM(hf, e) do {                                                  \
    int mi_ = (e) >> 3, ni_ = (((e) >> 2) & 1), q_ = (e) & 3;                 \
    float ev_ = ex2f(c[mi_][(hf) * 2 + ni_][q_]);                             \
    rowacc[mi_ * 2 + (q_ >> 1)] += ev_;                                       \
    colacc[((hf) * 2 + ni_) * 2 + (q_ & 1)] += ev_;                           \
} while (0)

// ---------------------------------------------------------------------------
// Kernel 2: upper-triangle HMMA + fused ex2 rowsum/colsum + fused finalize.
// Register-cached A fragments; triple-buffered B; ONE barrier per tile.
// ---------------------------------------------------------------------------
__global__ void __launch_bounds__(NTHREADS, 1) simsum_tri_kernel(float* __restrict__ out) {
    extern __shared__ char smem[];
    const uint32_t sbase = smem_u32(smem);
    const int tid  = threadIdx.x;
    const int lane = tid & 31;
    const int wid  = tid >> 5;
    const int wm = wid >> 2;
    const int wn = wid & 3;
    const int bid = blockIdx.x;

    const int cnt   = 14 + (bid < 8 ? 1 : 0);
    const int start = bid * 14 + (bid < 8 ? bid : 8);

    int r;
    {
        float fr = (129.0f - sqrtf(129.0f * 129.0f - 8.0f * (float)start)) * 0.5f;
        r = (int)fr;
        if (r < 0) r = 0;
        if (r > 63) r = 63;
        while (r < 63 && (r + 1) * (129 - (r + 1)) / 2 <= start) ++r;
        while (r > 0 && r * (129 - r) / 2 > start) --r;
    }
    int j = r + (start - r * (129 - r) / 2);

    const uint32_t a_base = sbase + OFF_A +
        (uint32_t)((wm * 64 + (lane & 15)) * LDS_BYTES + (lane >> 4) * 16);
    const uint32_t b_base_rel =
        (uint32_t)((wn * 32 + (lane & 15)) * LDS_BYTES + (lane >> 4) * 16);
    const int groupid = lane >> 2;
    const uint32_t boff[3] = {OFF_B0, OFF_B1, OFF_B2};

    // prefetch B tile for j into buf 0 (full tile: 2048 x 16B)
    #pragma unroll
    for (int it = 0; it < 8; ++it) {
        int idx = it * NTHREADS + tid;
        int rr = idx >> 4, cc = idx & 15;
        const char* src = (const char*)(g_Zbf16 + (j * 128 + rr) * D + cc * 8);
        CP_ASYNC16(sbase + OFF_B0 + rr * LDS_BYTES + cc * 16, src);
    }
    CP_COMMIT();

    // load A strip r (scaled, full tile), cache fragments in registers
    uint32_t afr[8][4][4];
    {
        #pragma unroll
        for (int it = 0; it < 8; ++it) {
            int idx = it * NTHREADS + tid;
            int rr = idx >> 4, cc = idx & 15;
            uint4 v = *(const uint4*)(g_Zbf16s + (r * 128 + rr) * D + cc * 8);
            *(uint4*)(smem + OFF_A + rr * LDS_BYTES + cc * 16) = v;
        }
        __syncthreads();
        #pragma unroll
        for (int ks = 0; ks < 8; ++ks)
            #pragma unroll
            for (int mi = 0; mi < 4; ++mi)
                LDM_X4(afr[ks][mi][0], afr[ks][mi][1], afr[ks][mi][2], afr[ks][mi][3],
                       a_base + (uint32_t)(mi * 16 * LDS_BYTES + ks * 32));
    }

    float rowacc[8];
    #pragma unroll
    for (int i = 0; i < 8; ++i) rowacc[i] = 0.0f;

    int bufsel = 0;
    for (int t = 0; t < cnt; ++t) {
        int rn = r, jn = j + 1;
        if (jn >= NRB) { rn = r + 1; jn = rn; }
        int bufnext = (bufsel == 2) ? 0 : bufsel + 1;

        if (t + 1 < cnt) {
            uint32_t bdst = sbase + boff[bufnext];
            #pragma unroll
            for (int it = 0; it < 8; ++it) {
                int idx = it * NTHREADS + tid;
                int rr = idx >> 4, cc = idx & 15;
                const char* src = (const char*)(g_Zbf16 + (jn * 128 + rr) * D + cc * 8);
                CP_ASYNC16(bdst + rr * LDS_BYTES + cc * 16, src);
            }
            CP_COMMIT();
            CP_WAIT(1);
        } else {
            CP_WAIT(0);
        }
        __syncthreads();   // single barrier per tile: publishes B[t], guards buf reuse

        const uint32_t b_base = sbase + boff[bufsel] + b_base_rel;

        float c[4][4][4];
        float colacc[8];
        #pragma unroll
        for (int i = 0; i < 8; ++i) colacc[i] = 0.0f;

        // ---- pass 0: MMA for ni = 0..1 ----
        #pragma unroll
        for (int mi = 0; mi < 4; ++mi)
            #pragma unroll
            for (int ni = 0; ni < 2; ++ni)
                #pragma unroll
                for (int q = 0; q < 4; ++q) c[mi][ni][q] = 0.0f;
        #pragma unroll
        for (int ks = 0; ks < 8; ++ks) {
            uint32_t b0[4];
            LDM_X4(b0[0], b0[1], b0[2], b0[3], b_base + (uint32_t)(ks * 32));
            #pragma unroll
            for (int mi = 0; mi < 4; ++mi)
                #pragma unroll
                for (int ni = 0; ni < 2; ++ni)
                    MMA_BF16(c[mi][ni][0], c[mi][ni][1], c[mi][ni][2], c[mi][ni][3],
                             afr[ks][mi][0], afr[ks][mi][1], afr[ks][mi][2], afr[ks][mi][3],
                             b0[ni], b0[ni + 2]);
        }

        // ---- pass 1: MMA for ni = 2..3 with half0 epilogue interleaved ----
        #pragma unroll
        for (int mi = 0; mi < 4; ++mi)
            #pragma unroll
            for (int ni = 2; ni < 4; ++ni)
                #pragma unroll
                for (int q = 0; q < 4; ++q) c[mi][ni][q] = 0.0f;
        #pragma unroll
        for (int ks = 0; ks < 8; ++ks) {
            uint32_t b1[4];
            LDM_X4(b1[0], b1[1], b1[2], b1[3],
                   b_base + (uint32_t)(16 * LDS_BYTES + ks * 32));
            #pragma unroll
            for (int mi = 0; mi < 4; ++mi)
                #pragma unroll
                for (int ni = 0; ni < 2; ++ni)
                    MMA_BF16(c[mi][ni + 2][0], c[mi][ni + 2][1], c[mi][ni + 2][2], c[mi][ni + 2][3],
                             afr[ks][mi][0], afr[ks][mi][1], afr[ks][mi][2], afr[ks][mi][3],
                             b1[ni], b1[ni + 2]);
            EPI_ELEM(0, ks * 4 + 0);
            EPI_ELEM(0, ks * 4 + 1);
            EPI_ELEM(0, ks * 4 + 2);
            EPI_ELEM(0, ks * 4 + 3);
        }

        // ---- half1 epilogue tail ----
        #pragma unroll
        for (int e = 0; e < 32; ++e) EPI_ELEM(1, e);

        // flush colsums unless diagonal tile
        if (j != r) {
            #pragma unroll
            for (int i = 0; i < 8; ++i) {
                colacc[i] += __shfl_xor_sync(0xFFFFFFFFu, colacc[i], 4);
                colacc[i] += __shfl_xor_sync(0xFFFFFFFFu, colacc[i], 8);
                colacc[i] += __shfl_xor_sync(0xFFFFFFFFu, colacc[i], 16);
            }
            if (lane < 4) {
                int cb = j * 128 + wn * 32 + 2 * lane;
                #pragma unroll
                for (int ni = 0; ni < 4; ++ni) {
                    atomicAdd(&g_denom[cb + ni * 8 + 0], colacc[ni * 2 + 0]);
                    atomicAdd(&g_denom[cb + ni * 8 + 1], colacc[ni * 2 + 1]);
                }
            }
        }

        // strip change: flush rowsums, reload A for rn (rare: <=1 per block)
        if (t + 1 < cnt && rn != r) {
            #pragma unroll
            for (int i = 0; i < 8; ++i) {
                rowacc[i] += __shfl_xor_sync(0xFFFFFFFFu, rowacc[i], 1);
                rowacc[i] += __shfl_xor_sync(0xFFFFFFFFu, rowacc[i], 2);
            }
            if ((lane & 3) == 0) {
                int rb = r * 128 + wm * 64 + groupid;
                #pragma unroll
                for (int mi = 0; mi < 4; ++mi) {
                    atomicAdd(&g_denom[rb + mi * 16 + 0], rowacc[mi * 2 + 0]);
                    atomicAdd(&g_denom[rb + mi * 16 + 8], rowacc[mi * 2 + 1]);
                }
            }
            #pragma unroll
            for (int i = 0; i < 8; ++i) rowacc[i] = 0.0f;

            __syncthreads();   // all warps done with prior A-smem reads
            #pragma unroll
            for (int it = 0; it < 8; ++it) {
                int idx = it * NTHREADS + tid;
                int rr = idx >> 4, cc = idx & 15;
                uint4 v = *(const uint4*)(g_Zbf16s + (rn * 128 + rr) * D + cc * 8);
                *(uint4*)(smem + OFF_A + rr * LDS_BYTES + cc * 16) = v;
            }
            __syncthreads();
            #pragma unroll
            for (int ks = 0; ks < 8; ++ks)
                #pragma unroll
                for (int mi = 0; mi < 4; ++mi)
                    LDM_X4(afr[ks][mi][0], afr[ks][mi][1], afr[ks][mi][2], afr[ks][mi][3],
                           a_base + (uint32_t)(mi * 16 * LDS_BYTES + ks * 32));
        }

        r = rn; j = jn;
        bufsel = bufnext;
    }

    // final rowsum flush (strip of last processed tile)
    #pragma unroll
    for (int i = 0; i < 8; ++i) {
        rowacc[i] += __shfl_xor_sync(0xFFFFFFFFu, rowacc[i], 1);
        rowacc[i] += __shfl_xor_sync(0xFFFFFFFFu, rowacc[i], 2);
    }
    if ((lane & 3) == 0) {
        int lastidx = start + cnt - 1;
        int rr2;
        {
            float fr = (129.0f - sqrtf(129.0f * 129.0f - 8.0f * (float)lastidx)) * 0.5f;
            rr2 = (int)fr;
            if (rr2 < 0) rr2 = 0;
            if (rr2 > 63) rr2 = 63;
            while (rr2 < 63 && (rr2 + 1) * (129 - (rr2 + 1)) / 2 <= lastidx) ++rr2;
            while (rr2 > 0 && rr2 * (129 - rr2) / 2 > lastidx) --rr2;
        }
        int rb = rr2 * 128 + wm * 64 + groupid;
        #pragma unroll
        for (int mi = 0; mi < 4; ++mi) {
            atomicAdd(&g_denom[rb + mi * 16 + 0], rowacc[mi * 2 + 0]);
            atomicAdd(&g_denom[rb + mi * 16 + 8], rowacc[mi * 2 + 1]);
        }
    }

    // ---- fused finalize: last CTA computes the loss ----
    __shared__ unsigned int s_islast;
    __threadfence();
    __syncthreads();
    if (tid == 0)
        s_islast = (atomicAdd(&g_done, 1u) == NCTAS - 1) ? 1u : 0u;
    __syncthreads();

    if (s_islast) {
        __shared__ float red[NTHREADS];
        float s = 0.0f;
        for (int rr = tid; rr < TWO_B; rr += NTHREADS) {
            float denom = __ldcg(&g_denom[rr]) - 7.3890560989306495f;
            float pos = g_pos[rr & (BSZ - 1)];
            s += __logf(fmaxf(denom, 1e-20f)) - 2.0f * pos;
        }
        red[tid] = s;
        __syncthreads();
        #pragma unroll
        for (int st = NTHREADS / 2; st > 0; st >>= 1) {
            if (tid < st) red[tid] += red[tid + st];
            __syncthreads();
        }
        if (tid == 0) {
            out[0] = red[0] / (float)TWO_B;
            g_done = 0;     // reset for next graph replay
        }
    }
}

// ---------------------------------------------------------------------------
extern "C" void kernel_launch(void* const* d_in, const int* in_sizes, int n_in,
                              void* d_out, int out_size) {
    const float* p1 = (const float*)d_in[0];
    const float* p2 = (const float*)d_in[1];
    float* out = (float*)d_out;
    (void)in_sizes; (void)n_in; (void)out_size;

    cudaFuncSetAttribute(simsum_tri_kernel,
                         cudaFuncAttributeMaxDynamicSharedMemorySize,
                         SMEM_TOTAL);

    normalize_kernel<<<BSZ / 8, 256>>>(p1, p2);
    simsum_tri_kernel<<<NCTAS, NTHREADS, SMEM_TOTAL>>>(out);
}